// round 14
// baseline (speedup 1.0000x reference)
#include <cuda_runtime.h>
#include <math_constants.h>

// Problem constants
#define NTOK 32768
#define TPB 256             // thread t owns d-pair (2t, 2t+1)
#define GRID 296            // 148 SMs * 2 CTAs
#define TPI 3               // tokens per iteration
#define STRIDE (GRID * TPI) // 888

// Dynamic smem layout (bytes):
//   stages [3][TPI tok][2 kpair][256 thr][16B]  : 73728   (pair01 at +0, pair23 at +4096)
//   s_part [TPI tok][8 warp][4 grp][4 pair] u64 : 3072    (off 73728)
//   wk     [2 parity][2 kind][TPI][2] u64       : 192     (off 76800)
#define ST_OFF 0
#define STG_SZ 24576
#define SP_OFF 73728
#define WK_OFF 76800
#define SMEM_BYTES 76992

typedef unsigned long long u64;

__device__ __forceinline__ u64 pack2(float lo, float hi) {
    u64 r; asm("mov.b64 %0, {%1, %2};" : "=l"(r) : "f"(lo), "f"(hi)); return r;
}
__device__ __forceinline__ void unpack2(u64 v, float& lo, float& hi) {
    asm("mov.b64 {%0, %1}, %2;" : "=f"(lo), "=f"(hi) : "l"(v));
}
__device__ __forceinline__ void fma2(u64& d, u64 a, u64 b) {
    asm("fma.rn.f32x2 %0, %1, %2, %0;" : "+l"(d) : "l"(a), "l"(b));
}
__device__ __forceinline__ u64 add2(u64 a, u64 b) {
    u64 r; asm("add.rn.f32x2 %0, %1, %2;" : "=l"(r) : "l"(a), "l"(b)); return r;
}
__device__ __forceinline__ u64 shfl_xor_u64(u64 v, int off) {
    float lo, hi; unpack2(v, lo, hi);
    lo = __shfl_xor_sync(0xffffffffu, lo, off);
    hi = __shfl_xor_sync(0xffffffffu, hi, off);
    return pack2(lo, hi);
}
__device__ __forceinline__ void cp8(unsigned dst, const void* src) {
    asm volatile("cp.async.ca.shared.global [%0], [%1], 8;"
                 :: "r"(dst), "l"(src) : "memory");
}
__device__ __forceinline__ void cp_commit() {
    asm volatile("cp.async.commit_group;" ::: "memory");
}
__device__ __forceinline__ void cp_wait1() {
    asm volatile("cp.async.wait_group 1;" ::: "memory");
}

__global__ void __launch_bounds__(TPB, 2)
router_kernel(const float* __restrict__ m0, const float* __restrict__ m1,
              const float* __restrict__ m2, const float* __restrict__ m3,
              const float* __restrict__ Wtop, const float* __restrict__ btop,
              const float* __restrict__ Wsoft, const float* __restrict__ bsoft,
              const float* __restrict__ alpha, float* __restrict__ out)
{
    extern __shared__ __align__(16) char sm[];
    unsigned sm_u32;
    asm("{ .reg .u64 tmp; cvta.to.shared.u64 tmp, %1; cvt.u32.u64 %0, tmp; }"
        : "=r"(sm_u32) : "l"(sm));

    const int t = threadIdx.x;
    const int wid = t >> 5;
    const int lane = t & 31;

    // ---- One-time: weights for (d0,d1)=(2t,2t+1), packed f32x2 ----
    u64 w[8][4];
    {
        const float4* Wt4 = (const float4*)Wtop;
        const float4* Ws4 = (const float4*)Wsoft;
        #pragma unroll
        for (int j = 0; j < 4; j++) {
            float4 a0 = Wt4[j * 512 + 2 * t];
            float4 a1 = Wt4[j * 512 + 2 * t + 1];
            w[j][0] = pack2(a0.x, a1.x);
            w[j][1] = pack2(a0.y, a1.y);
            w[j][2] = pack2(a0.z, a1.z);
            w[j][3] = pack2(a0.w, a1.w);
            float4 b0 = Ws4[j * 512 + 2 * t];
            float4 b1 = Ws4[j * 512 + 2 * t + 1];
            w[4 + j][0] = pack2(b0.x, b1.x);
            w[4 + j][1] = pack2(b0.y, b1.y);
            w[4 + j][2] = pack2(b0.z, b1.z);
            w[4 + j][3] = pack2(b0.w, b1.w);
        }
    }
    const float aSig = 1.0f / (1.0f + __expf(-alpha[0]));
    const float aInv = 1.0f - aSig;

    const u64* q0 = (const u64*)m0;
    const u64* q1 = (const u64*)m1;
    const u64* q2 = (const u64*)m2;
    const u64* q3 = (const u64*)m3;
    u64* qo = (u64*)out;

    const int tok_b = blockIdx.x * TPI;
    const unsigned st_t = sm_u32 + ST_OFF + t * 16;   // this thread's 16B slot base

    // ---- Prologue: issue stages 0 and 1 (thread-private slots) ----
    #pragma unroll
    for (int s = 0; s < 2; s++) {
        int tk0 = tok_b + s * STRIDE;
        #pragma unroll
        for (int i = 0; i < TPI; i++) {
            int tk = tk0 + i;
            if (tk < NTOK) {
                int base = tk * 256 + t;
                unsigned d = st_t + s * STG_SZ + i * 8192;
                cp8(d,        q0 + base);
                cp8(d + 8,    q1 + base);
                cp8(d + 4096, q2 + base);
                cp8(d + 4104, q3 + base);
            }
        }
        cp_commit();
    }

    int sn = 0;      // current stage = n % 3
    int q = 0;       // parity = n & 1
    int tok0 = tok_b;
    for (; tok0 < NTOK; tok0 += STRIDE) {
        // ---- Wait this thread's current tile (thread-private; no barrier) ----
        cp_wait1();

        // ---- GEMV + warp pre-reduce for TPI tokens ----
        #pragma unroll
        for (int i = 0; i < TPI; i++) {
            const char* sb = sm + (size_t)(ST_OFF + sn * STG_SZ + i * 8192) + t * 16;
            ulonglong2 v01 = *(const ulonglong2*)(sb);          // (m0, m1)
            ulonglong2 v23 = *(const ulonglong2*)(sb + 4096);   // (m2, m3)

            u64 acc[4];
            #pragma unroll
            for (int p = 0; p < 4; p++) acc[p] = 0ull;
            // acc[p] accumulates logits (2p, 2p+1): reduce (d0,d1) later
            u64 a8[8];
            #pragma unroll
            for (int j = 0; j < 8; j++) a8[j] = 0ull;
            #pragma unroll
            for (int j = 0; j < 8; j++) fma2(a8[j], v01.x, w[j][0]);
            #pragma unroll
            for (int j = 0; j < 8; j++) fma2(a8[j], v01.y, w[j][1]);
            #pragma unroll
            for (int j = 0; j < 8; j++) fma2(a8[j], v23.x, w[j][2]);
            #pragma unroll
            for (int j = 0; j < 8; j++) fma2(a8[j], v23.y, w[j][3]);
            #pragma unroll
            for (int p = 0; p < 4; p++) {
                float x0, x1, y0, y1;
                unpack2(a8[2 * p],     x0, x1);
                unpack2(a8[2 * p + 1], y0, y1);
                acc[p] = pack2(x0 + x1, y0 + y1);
            }

            // 3-step butterfly: every 8-lane group holds its group sum
            #pragma unroll
            for (int off = 1; off <= 4; off <<= 1) {
                #pragma unroll
                for (int p = 0; p < 4; p++)
                    acc[p] = add2(acc[p], shfl_xor_u64(acc[p], off));
            }
            if ((lane & 7) == 0) {
                char* dst = sm + (size_t)SP_OFF +
                            (size_t)(((i * 8 + wid) * 4 + (lane >> 3)) * 32);
                *(ulonglong2*)dst        = make_ulonglong2(acc[0], acc[1]);
                *(ulonglong2*)(dst + 16) = make_ulonglong2(acc[2], acc[3]);
            }
        }

        // ---- SINGLE barrier: publishes partials(n) and wk(n-1) ----
        __syncthreads();

        // ---- Stage-2 reduce + routing(n): warps 0..5 -> (i = w>>1, h = w&1)
        if (wid < 2 * TPI) {
            const int i = wid >> 1;
            const int h = wid & 1;          // 0: top/hard, 1: soft
            // lane = w*4+g reads its (warp, group) sums for pairs (2h, 2h+1)
            const char* src = sm + (size_t)SP_OFF + (size_t)(i * 1024 + lane * 32 + h * 16);
            ulonglong2 v = *(const ulonglong2*)src;
            u64 r0 = v.x, r1 = v.y;
            #pragma unroll
            for (int off = 16; off > 0; off >>= 1) {
                r0 = add2(r0, shfl_xor_u64(r0, off));
                r1 = add2(r1, shfl_xor_u64(r1, off));
            }
            float L0, L1, L2, L3;
            unpack2(r0, L0, L1);
            unpack2(r1, L2, L3);

            char* wkp = sm + (size_t)WK_OFF + (size_t)(((q * 2 + h) * TPI + i) * 16);
            if (h == 0) {
                L0 += btop[0]; L1 += btop[1]; L2 += btop[2]; L3 += btop[3];
                float Tv[4] = {L0, L1, L2, L3};
                int i1 = 0; float v1 = Tv[0];
                #pragma unroll
                for (int k = 1; k < 4; k++) if (Tv[k] > v1) { v1 = Tv[k]; i1 = k; }
                int i2 = -1; float v2 = -CUDART_INF_F;
                #pragma unroll
                for (int k = 0; k < 4; k++) if (k != i1 && Tv[k] > v2) { v2 = Tv[k]; i2 = k; }
                float pp1 = aSig / (1.0f + __expf(v2 - v1));
                float pp2 = aSig - pp1;
                float hk[4];
                #pragma unroll
                for (int k = 0; k < 4; k++)
                    hk[k] = (k == i1) ? pp1 : ((k == i2) ? pp2 : 0.0f);
                if (lane == 0) {
                    *(u64*)(wkp)     = pack2(hk[0], hk[1]);
                    *(u64*)(wkp + 8) = pack2(hk[2], hk[3]);
                }
            } else {
                L0 += bsoft[0]; L1 += bsoft[1]; L2 += bsoft[2]; L3 += bsoft[3];
                float ms = fmaxf(fmaxf(L0, L1), fmaxf(L2, L3));
                float e0 = __expf(L0 - ms), e1 = __expf(L1 - ms);
                float e2 = __expf(L2 - ms), e3 = __expf(L3 - ms);
                float sc = aInv / (e0 + e1 + e2 + e3);
                if (lane == 0) {
                    *(u64*)(wkp)     = pack2(e0 * sc, e1 * sc);
                    *(u64*)(wkp + 8) = pack2(e2 * sc, e3 * sc);
                }
            }
        }

        // ---- Epilogue(n-1): wk[1-q], m from stage (sn+2)%3 (thread-own slots)
        if (tok0 != tok_b) {
            const int tokp = tok0 - STRIDE;
            const int sp = (sn + 2) % 3;
            #pragma unroll
            for (int i = 0; i < TPI; i++) {
                int tk = tokp + i;
                if (tk < NTOK) {
                    const char* sb = sm + (size_t)(ST_OFF + sp * STG_SZ + i * 8192) + t * 16;
                    ulonglong2 v01 = *(const ulonglong2*)(sb);
                    ulonglong2 v23 = *(const ulonglong2*)(sb + 4096);
                    const char* wh = sm + (size_t)WK_OFF + (size_t)((((1 - q) * 2 + 0) * TPI + i) * 16);
                    const char* ws = sm + (size_t)WK_OFF + (size_t)((((1 - q) * 2 + 1) * TPI + i) * 16);
                    float w0, w1, w2, w3;
                    unpack2(add2(*(const u64*)wh,       *(const u64*)ws),       w0, w1);
                    unpack2(add2(*(const u64*)(wh + 8), *(const u64*)(ws + 8)), w2, w3);
                    u64 o = 0ull;
                    fma2(o, v01.x, pack2(w0, w0));
                    fma2(o, v01.y, pack2(w1, w1));
                    fma2(o, v23.x, pack2(w2, w2));
                    fma2(o, v23.y, pack2(w3, w3));
                    qo[tk * 256 + t] = o;
                }
            }
        }

        // ---- Prefetch(n+2) into stage (sn+2)%3 (own slots; after own epilogue reads)
        {
            int tk0 = tok0 + 2 * STRIDE;
            #pragma unroll
            for (int i = 0; i < TPI; i++) {
                int tk = tk0 + i;
                if (tk < NTOK) {
                    int base = tk * 256 + t;
                    unsigned d = st_t + ((sn + 2) % 3) * STG_SZ + i * 8192;
                    cp8(d,        q0 + base);
                    cp8(d + 8,    q1 + base);
                    cp8(d + 4096, q2 + base);
                    cp8(d + 4104, q3 + base);
                }
            }
            cp_commit();
        }

        sn = (sn + 1) % 3;
        q ^= 1;
    }

    // ---- Final epilogue for the last iteration's tokens ----
    __syncthreads();
    {
        const int tokp = tok0 - STRIDE;           // last executed iteration
        const int sp = (sn + 2) % 3;              // its stage
        const int qp = 1 - q;                     // its parity
        #pragma unroll
        for (int i = 0; i < TPI; i++) {
            int tk = tokp + i;
            if (tk >= 0 && tk < NTOK) {
                const char* sb = sm + (size_t)(ST_OFF + sp * STG_SZ + i * 8192) + t * 16;
                ulonglong2 v01 = *(const ulonglong2*)(sb);
                ulonglong2 v23 = *(const ulonglong2*)(sb + 4096);
                const char* wh = sm + (size_t)WK_OFF + (size_t)(((qp * 2 + 0) * TPI + i) * 16);
                const char* ws = sm + (size_t)WK_OFF + (size_t)(((qp * 2 + 1) * TPI + i) * 16);
                float w0, w1, w2, w3;
                unpack2(add2(*(const u64*)wh,       *(const u64*)ws),       w0, w1);
                unpack2(add2(*(const u64*)(wh + 8), *(const u64*)(ws + 8)), w2, w3);
                u64 o = 0ull;
                fma2(o, v01.x, pack2(w0, w0));
                fma2(o, v01.y, pack2(w1, w1));
                fma2(o, v23.x, pack2(w2, w2));
                fma2(o, v23.y, pack2(w3, w3));
                qo[tk * 256 + t] = o;
            }
        }
    }
}

extern "C" void kernel_launch(void* const* d_in, const int* in_sizes, int n_in,
                              void* d_out, int out_size) {
    (void)in_sizes; (void)n_in; (void)out_size;
    cudaFuncSetAttribute(router_kernel,
                         cudaFuncAttributeMaxDynamicSharedMemorySize, SMEM_BYTES);
    router_kernel<<<GRID, TPB, SMEM_BYTES>>>(
        (const float*)d_in[0], (const float*)d_in[1],
        (const float*)d_in[2], (const float*)d_in[3],
        (const float*)d_in[4], (const float*)d_in[5],
        (const float*)d_in[6], (const float*)d_in[7],
        (const float*)d_in[8], (float*)d_out);
}

// round 15
// speedup vs baseline: 1.1009x; 1.1009x over previous
#include <cuda_runtime.h>
#include <math_constants.h>

// Problem constants
#define NTOK 32768
#define TPB 256             // thread t owns d-pair (2t, 2t+1)
#define GRID 296            // 148 SMs * 2 CTAs
#define TPI 2               // tokens per iteration
#define STRIDE (GRID * TPI) // 592

typedef unsigned long long u64;

__device__ __forceinline__ u64 pack2(float lo, float hi) {
    u64 r; asm("mov.b64 %0, {%1, %2};" : "=l"(r) : "f"(lo), "f"(hi)); return r;
}
__device__ __forceinline__ void unpack2(u64 v, float& lo, float& hi) {
    asm("mov.b64 {%0, %1}, %2;" : "=f"(lo), "=f"(hi) : "l"(v));
}
__device__ __forceinline__ void fma2(u64& d, u64 a, u64 b) {
    asm("fma.rn.f32x2 %0, %1, %2, %0;" : "+l"(d) : "l"(a), "l"(b));
}
__device__ __forceinline__ u64 add2(u64 a, u64 b) {
    u64 r; asm("add.rn.f32x2 %0, %1, %2;" : "=l"(r) : "l"(a), "l"(b)); return r;
}
__device__ __forceinline__ u64 shfl_xor_u64(u64 v, int off) {
    float lo, hi; unpack2(v, lo, hi);
    lo = __shfl_xor_sync(0xffffffffu, lo, off);
    hi = __shfl_xor_sync(0xffffffffu, hi, off);
    return pack2(lo, hi);
}

__global__ void __launch_bounds__(TPB, 2)
router_kernel(const float* __restrict__ m0, const float* __restrict__ m1,
              const float* __restrict__ m2, const float* __restrict__ m3,
              const float* __restrict__ Wtop, const float* __restrict__ btop,
              const float* __restrict__ Wsoft, const float* __restrict__ bsoft,
              const float* __restrict__ alpha, float* __restrict__ out)
{
    // Partials ping-pong by parity: closes the STS(n+1) vs routing-read(n) race.
    __shared__ u64 s_part[2][TPI][4][TPB];        // 32 KB
    __shared__ u64 s_wk[2][2][TPI][2];            // [parity][hard/soft][token][pair]

    const int t = threadIdx.x;
    const int wid = t >> 5;
    const int lane = t & 31;

    // ---- One-time: weights for (d0,d1)=(2t,2t+1), packed f32x2 ----
    u64 w[8][4];
    {
        const float4* Wt4 = (const float4*)Wtop;
        const float4* Ws4 = (const float4*)Wsoft;
        #pragma unroll
        for (int j = 0; j < 4; j++) {
            float4 a0 = Wt4[j * 512 + 2 * t];
            float4 a1 = Wt4[j * 512 + 2 * t + 1];
            w[j][0] = pack2(a0.x, a1.x);
            w[j][1] = pack2(a0.y, a1.y);
            w[j][2] = pack2(a0.z, a1.z);
            w[j][3] = pack2(a0.w, a1.w);
            float4 b0 = Ws4[j * 512 + 2 * t];
            float4 b1 = Ws4[j * 512 + 2 * t + 1];
            w[4 + j][0] = pack2(b0.x, b1.x);
            w[4 + j][1] = pack2(b0.y, b1.y);
            w[4 + j][2] = pack2(b0.z, b1.z);
            w[4 + j][3] = pack2(b0.w, b1.w);
        }
    }
    const float aSig = 1.0f / (1.0f + __expf(-alpha[0]));
    const float aInv = 1.0f - aSig;

    const u64* q0 = (const u64*)m0;
    const u64* q1 = (const u64*)m1;
    const u64* q2 = (const u64*)m2;
    const u64* q3 = (const u64*)m3;
    u64* qo = (u64*)out;

    const int tok_b = blockIdx.x * TPI;

    u64 dmP[TPI][4], dmC[TPI][4], dmN[TPI][4];

    // ---- Prologue: load iter-0 tokens into dmC ----
    #pragma unroll
    for (int i = 0; i < TPI; i++) {
        int base = (tok_b + i) * 256 + t;       // tok_b+i always < NTOK
        dmC[i][0] = q0[base]; dmC[i][1] = q1[base];
        dmC[i][2] = q2[base]; dmC[i][3] = q3[base];
    }

    int q = 0;
    int tok0 = tok_b;
    for (; tok0 < NTOK; tok0 += STRIDE, q ^= 1) {
        // ---- 1. Prefetch iter n+1 into dmN (a full iteration of latency slack)
        {
            int nt0 = tok0 + STRIDE;
            #pragma unroll
            for (int i = 0; i < TPI; i++) {
                int tk = nt0 + i;
                if (tk < NTOK) {
                    int base = tk * 256 + t;
                    dmN[i][0] = q0[base]; dmN[i][1] = q1[base];
                    dmN[i][2] = q2[base]; dmN[i][3] = q3[base];
                }
            }
        }

        // ---- 2. GEMV(cur): 8 logits per token, packed f32x2; STS partials[q]
        #pragma unroll
        for (int i = 0; i < TPI; i++) {
            u64 a8[8];
            #pragma unroll
            for (int j = 0; j < 8; j++) a8[j] = 0ull;
            #pragma unroll
            for (int k = 0; k < 4; k++) {
                #pragma unroll
                for (int j = 0; j < 8; j++) fma2(a8[j], dmC[i][k], w[j][k]);
            }
            #pragma unroll
            for (int p = 0; p < 4; p++) {
                float x0, x1, y0, y1;
                unpack2(a8[2 * p],     x0, x1);
                unpack2(a8[2 * p + 1], y0, y1);
                s_part[q][i][p][t] = pack2(x0 + x1, y0 + y1);
            }
        }

        // ---- 3. SINGLE barrier: publishes partials[q] and wk[1-q] ----
        __syncthreads();

        // ---- 4. Reduce + routing(n): warps 0..3 -> (i = w>>1, h = w&1) ----
        if (wid < 2 * TPI) {
            const int i = wid >> 1;
            const int h = wid & 1;          // 0: top/hard, 1: soft
            const ulonglong2* rowa = (const ulonglong2*)&s_part[q][i][2 * h][0];
            const ulonglong2* rowb = (const ulonglong2*)&s_part[q][i][2 * h + 1][0];
            ulonglong2 a0 = rowa[lane],      a1 = rowa[lane + 32];
            ulonglong2 a2 = rowa[lane + 64], a3 = rowa[lane + 96];
            ulonglong2 b0 = rowb[lane],      b1 = rowb[lane + 32];
            ulonglong2 b2 = rowb[lane + 64], b3 = rowb[lane + 96];
            u64 r0 = add2(add2(add2(a0.x, a0.y), add2(a1.x, a1.y)),
                          add2(add2(a2.x, a2.y), add2(a3.x, a3.y)));
            u64 r1 = add2(add2(add2(b0.x, b0.y), add2(b1.x, b1.y)),
                          add2(add2(b2.x, b2.y), add2(b3.x, b3.y)));
            #pragma unroll
            for (int off = 16; off > 0; off >>= 1) {
                r0 = add2(r0, shfl_xor_u64(r0, off));
                r1 = add2(r1, shfl_xor_u64(r1, off));
            }
            float L0, L1, L2, L3;
            unpack2(r0, L0, L1);
            unpack2(r1, L2, L3);

            if (h == 0) {
                L0 += btop[0]; L1 += btop[1]; L2 += btop[2]; L3 += btop[3];
                float Tv[4] = {L0, L1, L2, L3};
                int i1 = 0; float v1 = Tv[0];
                #pragma unroll
                for (int k = 1; k < 4; k++) if (Tv[k] > v1) { v1 = Tv[k]; i1 = k; }
                int i2 = -1; float v2 = -CUDART_INF_F;
                #pragma unroll
                for (int k = 0; k < 4; k++) if (k != i1 && Tv[k] > v2) { v2 = Tv[k]; i2 = k; }
                float pp1 = aSig / (1.0f + __expf(v2 - v1));
                float pp2 = aSig - pp1;
                float hk[4];
                #pragma unroll
                for (int k = 0; k < 4; k++)
                    hk[k] = (k == i1) ? pp1 : ((k == i2) ? pp2 : 0.0f);
                if (lane == 0) {
                    s_wk[q][0][i][0] = pack2(hk[0], hk[1]);
                    s_wk[q][0][i][1] = pack2(hk[2], hk[3]);
                }
            } else {
                L0 += bsoft[0]; L1 += bsoft[1]; L2 += bsoft[2]; L3 += bsoft[3];
                float ms = fmaxf(fmaxf(L0, L1), fmaxf(L2, L3));
                float e0 = __expf(L0 - ms), e1 = __expf(L1 - ms);
                float e2 = __expf(L2 - ms), e3 = __expf(L3 - ms);
                float sc = aInv / (e0 + e1 + e2 + e3);
                if (lane == 0) {
                    s_wk[q][1][i][0] = pack2(e0 * sc, e1 * sc);
                    s_wk[q][1][i][1] = pack2(e2 * sc, e3 * sc);
                }
            }
        }

        // ---- 5. Epilogue(n-1): dmP regs + wk[1-q] ----
        if (tok0 != tok_b) {
            const int tokp = tok0 - STRIDE;
            #pragma unroll
            for (int i = 0; i < TPI; i++) {
                int tk = tokp + i;          // previous iteration tokens: < NTOK by construction
                float w0, w1, w2, w3;
                unpack2(add2(s_wk[1 - q][0][i][0], s_wk[1 - q][1][i][0]), w0, w1);
                unpack2(add2(s_wk[1 - q][0][i][1], s_wk[1 - q][1][i][1]), w2, w3);
                u64 o = 0ull;
                fma2(o, dmP[i][0], pack2(w0, w0));
                fma2(o, dmP[i][1], pack2(w1, w1));
                fma2(o, dmP[i][2], pack2(w2, w2));
                fma2(o, dmP[i][3], pack2(w3, w3));
                qo[tk * 256 + t] = o;
            }
        }

        // ---- 6. Rotate register buffers ----
        #pragma unroll
        for (int i = 0; i < TPI; i++) {
            #pragma unroll
            for (int k = 0; k < 4; k++) {
                dmP[i][k] = dmC[i][k];
                dmC[i][k] = dmN[i][k];
            }
        }
    }

    // ---- Final epilogue: last executed iteration's tokens ----
    __syncthreads();
    {
        const int ql = q ^ 1;               // parity of last executed iteration
        const int tokp = tok0 - STRIDE;
        #pragma unroll
        for (int i = 0; i < TPI; i++) {
            int tk = tokp + i;
            if (tk < NTOK) {
                float w0, w1, w2, w3;
                unpack2(add2(s_wk[ql][0][i][0], s_wk[ql][1][i][0]), w0, w1);
                unpack2(add2(s_wk[ql][0][i][1], s_wk[ql][1][i][1]), w2, w3);
                u64 o = 0ull;
                fma2(o, dmP[i][0], pack2(w0, w0));
                fma2(o, dmP[i][1], pack2(w1, w1));
                fma2(o, dmP[i][2], pack2(w2, w2));
                fma2(o, dmP[i][3], pack2(w3, w3));
                qo[tk * 256 + t] = o;
            }
        }
    }
}

extern "C" void kernel_launch(void* const* d_in, const int* in_sizes, int n_in,
                              void* d_out, int out_size) {
    (void)in_sizes; (void)n_in; (void)out_size;
    router_kernel<<<GRID, TPB>>>(
        (const float*)d_in[0], (const float*)d_in[1],
        (const float*)d_in[2], (const float*)d_in[3],
        (const float*)d_in[4], (const float*)d_in[5],
        (const float*)d_in[6], (const float*)d_in[7],
        (const float*)d_in[8], (float*)d_out);
}